// round 12
// baseline (speedup 1.0000x reference)
#include <cuda_runtime.h>
#include <cuda_bf16.h>

#define NCAM 16

// Natural per-camera layout, 16 floats:
//   k 0..8: r00 r01 r02 r10 r11 r12 r20 r21 r22
//   k 9..11: t0 t1 t2   k 12,13: f0 f1   k 14,15: c0 c1
__constant__ __align__(16) float cparams[NCAM * 16];
__device__  __align__(16) float g_stage[NCAM * 16];

__device__ __forceinline__ float frcp(float x) {
    float r;
    asm("rcp.approx.f32 %0, %1;" : "=f"(r) : "f"(x));
    return r;
}

__global__ void prep_params_kernel(const float* __restrict__ R,
                                   const float* __restrict__ t,
                                   const float* __restrict__ f,
                                   const float* __restrict__ c)
{
    int s = threadIdx.x;
    if (s >= NCAM * 16) return;
    const int cam = s >> 4;
    const int k   = s & 15;
    float v;
    if (k < 9)       v = R[cam * 9 + k];
    else if (k < 12) v = t[cam * 3 + (k - 9)];
    else if (k < 14) v = f[cam * 2 + (k - 12)];
    else             v = c[cam * 2 + (k - 14)];
    g_stage[s] = v;
}

// Scalar math everywhere: camera params come from the constant bank with
// compile-time offsets (fully unrolled loop) -> ptxas emits LDCU into uniform
// registers on the dedicated uniform-const port (floor 1/cyc) and FFMA with UR
// operands. Zero shared memory, zero LDS -> the LSU/MIO pipe carries only the
// 3 LDG + 16 STG.128 that are fundamentally required.
__global__ __launch_bounds__(256, 6)
void Projection_19713899889207_kernel(
    const float* __restrict__ pt3d,   // (3, Np) SoA
    float* __restrict__ out,          // (NC*Np, 2)
    int np)
{
    const int i = blockIdx.x * blockDim.x + threadIdx.x;  // PAIR of points
    const int np2 = np >> 1;
    if (i >= np2) return;

    const float2 xy = __ldg(reinterpret_cast<const float2*>(pt3d) + i);
    const float2 yy = __ldg(reinterpret_cast<const float2*>(pt3d + (size_t)np) + i);
    const float2 zz = __ldg(reinterpret_cast<const float2*>(pt3d + 2 * (size_t)np) + i);
    const float x0 = xy.x, x1 = xy.y;
    const float y0 = yy.x, y1 = yy.y;
    const float z0 = zz.x, z1 = zz.y;

    // Output base for this pair; per-camera offsets are uniform (np in UR).
    char* o = reinterpret_cast<char*>(out) + (size_t)i * 16;
    const size_t cam_stride = (size_t)np * 8;

    #pragma unroll
    for (int cam = 0; cam < NCAM; ++cam) {
        const float* P = cparams + cam * 16;  // compile-time const-bank offset

        const float X0 = fmaf(P[0], x0, fmaf(P[1], y0, fmaf(P[2], z0, P[9])));
        const float X1 = fmaf(P[0], x1, fmaf(P[1], y1, fmaf(P[2], z1, P[9])));
        const float Y0 = fmaf(P[3], x0, fmaf(P[4], y0, fmaf(P[5], z0, P[10])));
        const float Y1 = fmaf(P[3], x1, fmaf(P[4], y1, fmaf(P[5], z1, P[10])));
        const float Z0 = fmaf(P[6], x0, fmaf(P[7], y0, fmaf(P[8], z0, P[11])));
        const float Z1 = fmaf(P[6], x1, fmaf(P[7], y1, fmaf(P[8], z1, P[11])));

        const float iz0 = frcp(Z0);
        const float iz1 = frcp(Z1);

        // u = (X*f0)*iz + c0,  v = (Y*f1)*iz + c1
        const float u0 = fmaf(X0 * P[12], iz0, P[14]);
        const float v0 = fmaf(Y0 * P[13], iz0, P[15]);
        const float u1 = fmaf(X1 * P[12], iz1, P[14]);
        const float v1 = fmaf(Y1 * P[13], iz1, P[15]);

        __stcs(reinterpret_cast<float4*>(o + (size_t)cam * cam_stride),
               make_float4(u0, v0, u1, v1));   // streaming STG.128
    }
}

extern "C" void kernel_launch(void* const* d_in, const int* in_sizes, int n_in,
                              void* d_out, int out_size)
{
    // metadata order: pt3d (3,Np) f32, R (16,3,3) f32, t (16,3) f32,
    //                 f (16,2) f32, c (16,2) f32, mask (16,Np) i32 (unused)
    const float* pt3d = (const float*)d_in[0];
    const float* R    = (const float*)d_in[1];
    const float* t    = (const float*)d_in[2];
    const float* f    = (const float*)d_in[3];
    const float* c    = (const float*)d_in[4];
    float* out        = (float*)d_out;

    const int np  = in_sizes[0] / 3;        // 2,000,000
    const int np2 = np / 2;

    // Stage params then copy into the constant bank (capturable D2D node).
    prep_params_kernel<<<1, 256>>>(R, t, f, c);
    void* stage_ptr = nullptr;
    cudaGetSymbolAddress(&stage_ptr, g_stage);
    cudaMemcpyToSymbolAsync(cparams, stage_ptr, NCAM * 16 * sizeof(float), 0,
                            cudaMemcpyDeviceToDevice);

    const int threads = 256;
    const int blocks  = (np2 + threads - 1) / threads;
    Projection_19713899889207_kernel<<<blocks, threads>>>(pt3d, out, np);
}